// round 14
// baseline (speedup 1.0000x reference)
#include <cuda_runtime.h>
#include <cuda_fp16.h>
#include <math.h>

#define N_NODES   100000
#define N_EDGES   1600000
#define N_FEAT    50
#define HIDDEN    16
#define N_CLASSES 10
#define CAP       64           // bucket capacity; deg ~ Poisson(16), P(>=64)~2e-18
#define E4        (N_EDGES / 4)

typedef unsigned long long ull;

// ---- packed f32x2 helpers (sm_103a) ----
__device__ __forceinline__ ull pk2(float lo, float hi) {
    ull r;
    asm("mov.b64 %0, {%1, %2};" : "=l"(r) : "f"(lo), "f"(hi));
    return r;
}
__device__ __forceinline__ void upk2(float& lo, float& hi, ull v) {
    asm("mov.b64 {%0, %1}, %2;" : "=f"(lo), "=f"(hi) : "l"(v));
}
__device__ __forceinline__ ull fma2(ull a, ull b, ull c) {
    ull d;
    asm("fma.rn.f32x2 %0, %1, %2, %3;" : "=l"(d) : "l"(a), "l"(b), "l"(c));
    return d;
}

// ---- scratch (static device globals; zero-initialized at load) ----
// payload arrays have ONE extra row (index N_NODES) that is never written:
// it stays zero and absorbs gathers for out-of-range bucket slots.
__device__ int   g_cnt[N_NODES];              // bucket fill counts (reset by agg2)
__device__ float g_dinv[N_NODES];
__device__ __align__(16) int g_csrp[N_NODES * CAP];  // padded bucket CSR (src ids)
__device__ __align__(16) float  g_xw0[N_NODES * HIDDEN];         // x@w1_0 + b1
__device__ __align__(16) __half g_xp1h[(N_NODES + 1) * HIDDEN];  // fp16 dinv*(x@w1_1)
__device__ __align__(16) float  g_hw [N_NODES * HIDDEN];         // h@w2_0 + b2
__device__ __align__(16) __half g_hph[(N_NODES + 1) * HIDDEN];   // fp16 dinv*(h@w2_1)

// ---- K1: single-pass bucket scatter; 4 edges/thread (stream 0) ----
__global__ void k_scatter1(const int* __restrict__ ei) {
    int e4 = blockIdx.x * blockDim.x + threadIdx.x;
    if (e4 >= E4) return;
    int4 s = ((const int4*)ei)[e4];
    int4 d = ((const int4*)(ei + N_EDGES))[e4];
    int p0 = atomicAdd(&g_cnt[d.x], 1);
    int p1 = atomicAdd(&g_cnt[d.y], 1);
    int p2 = atomicAdd(&g_cnt[d.z], 1);
    int p3 = atomicAdd(&g_cnt[d.w], 1);
    if (p0 < CAP) g_csrp[d.x * CAP + p0] = s.x;
    if (p1 < CAP) g_csrp[d.y * CAP + p1] = s.y;
    if (p2 < CAP) g_csrp[d.z * CAP + p2] = s.z;
    if (p3 < CAP) g_csrp[d.w * CAP + p3] = s.w;
}

// ---- K2: layer-1 projections, UNSCALED (no g_cnt dependency; runs || scatter) ----
__global__ void k_projU(const float* __restrict__ x,
                        const float* __restrict__ w0,
                        const float* __restrict__ w1,
                        const float* __restrict__ b1) {
    __shared__ ull sw0p[N_FEAT * HIDDEN / 2];
    __shared__ ull sw1p[N_FEAT * HIDDEN / 2];
    __shared__ float sb[HIDDEN];
    for (int i = threadIdx.x; i < N_FEAT * HIDDEN; i += blockDim.x) {
        ((float*)sw0p)[i] = w0[i];
        ((float*)sw1p)[i] = w1[i];
    }
    if (threadIdx.x < HIDDEN) sb[threadIdx.x] = b1[threadIdx.x];
    __syncthreads();

    int n = blockIdx.x * blockDim.x + threadIdx.x;
    if (n >= N_NODES) return;

    ull a0[8], a1[8];
    ull z = pk2(0.0f, 0.0f);
#pragma unroll
    for (int p = 0; p < 8; p++) { a0[p] = z; a1[p] = z; }

    const float2* xr = (const float2*)(x + (size_t)n * N_FEAT);  // 50 even
#pragma unroll 5
    for (int k2 = 0; k2 < N_FEAT / 2; k2++) {
        float2 xv = __ldg(&xr[k2]);
        ull xa = pk2(xv.x, xv.x);
        ull xb = pk2(xv.y, xv.y);
        const ull* w0a = sw0p + (2 * k2) * 8;
        const ull* w1a = sw1p + (2 * k2) * 8;
#pragma unroll
        for (int p = 0; p < 8; p++) {
            a0[p] = fma2(xa, w0a[p],     a0[p]);
            a0[p] = fma2(xb, w0a[8 + p], a0[p]);
            a1[p] = fma2(xa, w1a[p],     a1[p]);
            a1[p] = fma2(xb, w1a[8 + p], a1[p]);
        }
    }
    float4* o0 = (float4*)(g_xw0 + (size_t)n * HIDDEN);
    __half2 hx[8];
#pragma unroll
    for (int q = 0; q < 4; q++) {
        float v0a, v0b, v0c, v0d, v1a, v1b, v1c, v1d;
        upk2(v0a, v0b, a0[q * 2]);
        upk2(v0c, v0d, a0[q * 2 + 1]);
        upk2(v1a, v1b, a1[q * 2]);
        upk2(v1c, v1d, a1[q * 2 + 1]);
        float4 r0;
        r0.x = v0a + sb[q * 4 + 0];
        r0.y = v0b + sb[q * 4 + 1];
        r0.z = v0c + sb[q * 4 + 2];
        r0.w = v0d + sb[q * 4 + 3];
        o0[q] = r0;
        hx[q * 2 + 0] = __floats2half2_rn(v1a, v1b);
        hx[q * 2 + 1] = __floats2half2_rn(v1c, v1d);
    }
    uint4* oh = (uint4*)(g_xp1h + (size_t)n * HIDDEN);
    oh[0] = *(uint4*)&hx[0];
    oh[1] = *(uint4*)&hx[4];
}

// ---- K3: dinv from final cnt; scale xp1h in place (after join) ----
__global__ void k_scale() {
    int n = blockIdx.x * blockDim.x + threadIdx.x;
    if (n >= N_NODES) return;
    int d = g_cnt[n];
    float dn = (d > 0) ? rsqrtf((float)d) : 0.0f;
    g_dinv[n] = dn;
    uint4* p = (uint4*)(g_xp1h + (size_t)n * HIDDEN);
    uint4 v0 = p[0], v1 = p[1];
    __half2* h0 = (__half2*)&v0;
    __half2* h1 = (__half2*)&v1;
#pragma unroll
    for (int i = 0; i < 4; i++) {
        float2 f = __half22float2(h0[i]);
        h0[i] = __floats2half2_rn(dn * f.x, dn * f.y);
        f = __half22float2(h1[i]);
        h1[i] = __floats2half2_rn(dn * f.x, dn * f.y);
    }
    p[0] = v0;
    p[1] = v1;
}

// accumulate one uint2 payload (2 half2 = 4 channels) into float ac[4]
__device__ __forceinline__ void acc_h4(float* ac, uint2 v) {
    float2 f0 = __half22float2(*(__half2*)&v.x);
    float2 f1 = __half22float2(*(__half2*)&v.y);
    ac[0] += f0.x; ac[1] += f0.y; ac[2] += f1.x; ac[3] += f1.y;
}

// branch-free 16-edge gather chunk, uint2 payloads (4 channels per lane).
// bucket storage is always CAP ints; out-of-range slots -> zero row N_NODES.
__device__ __forceinline__ void gather16(const uint2* __restrict__ pay,
                                         const int* __restrict__ base,
                                         int j0, int len, int q, float* ac) {
    const int4* ip = (const int4*)(base + j0);
    int4 ia = __ldg(&ip[0]);
    int4 ib = __ldg(&ip[1]);
    int4 ic = __ldg(&ip[2]);
    int4 id = __ldg(&ip[3]);
    int s[16];
    s[0]  = ia.x; s[1]  = ia.y; s[2]  = ia.z; s[3]  = ia.w;
    s[4]  = ib.x; s[5]  = ib.y; s[6]  = ib.z; s[7]  = ib.w;
    s[8]  = ic.x; s[9]  = ic.y; s[10] = ic.z; s[11] = ic.w;
    s[12] = id.x; s[13] = id.y; s[14] = id.z; s[15] = id.w;
    uint2 v[16];
#pragma unroll
    for (int k = 0; k < 16; k++) {
        int idx = (j0 + k < len) ? s[k] : N_NODES;   // zero row if past end
        v[k] = __ldg(&pay[idx * 4 + q]);
    }
#pragma unroll
    for (int k = 0; k < 16; k++) acc_h4(ac, v[k]);
}

__device__ __forceinline__ void gather_all(const uint2* __restrict__ pay,
                                           int node, int q, int len,
                                           float* ac) {
    const int* base = g_csrp + node * CAP;
    gather16(pay, base, 0, len, q, ac);
    if (len > 16) {
        gather16(pay, base, 16, len, q, ac);
        if (len > 32) {
            gather16(pay, base, 32, len, q, ac);
            if (len > 48) gather16(pay, base, 48, len, q, ac);
        }
    }
}

// ---- K4: fused layer-1 agg + relu + layer-2 proj. 4 lanes/node ----
__global__ void __launch_bounds__(128, 8)
k_agg1p2(const float* __restrict__ w0,
         const float* __restrict__ w1,
         const float* __restrict__ b2) {
    __shared__ float sw0[HIDDEN][HIDDEN];   // [k][c], cols 10..15 = 0
    __shared__ float sw1[HIDDEN][HIDDEN];
    __shared__ float sb[HIDDEN];
    int t = threadIdx.x;
    for (int i = t; i < HIDDEN * HIDDEN; i += blockDim.x) {
        int k = i >> 4, c = i & 15;
        sw0[k][c] = (c < N_CLASSES) ? w0[k * N_CLASSES + c] : 0.0f;
        sw1[k][c] = (c < N_CLASSES) ? w1[k * N_CLASSES + c] : 0.0f;
    }
    if (t < HIDDEN) sb[t] = (t < N_CLASSES) ? b2[t] : 0.0f;
    __syncthreads();

    int gid  = blockIdx.x * blockDim.x + t;   // exactly N_NODES*4 threads
    int node = gid >> 2;
    int q    = gid & 3;                        // 4 channels per lane

    int len = g_cnt[node];
    float ac[4] = {0.f, 0.f, 0.f, 0.f};
    gather_all((const uint2*)g_xp1h, node, q, len, ac);

    float dn = g_dinv[node];
    float4 sf = ((const float4*)g_xw0)[node * 4 + q];
    float h[4];
    h[0] = fmaxf(sf.x + dn * ac[0], 0.0f);
    h[1] = fmaxf(sf.y + dn * ac[1], 0.0f);
    h[2] = fmaxf(sf.z + dn * ac[2], 0.0f);
    h[3] = fmaxf(sf.w + dn * ac[3], 0.0f);

    // layer-2 projection: channels q*4..q*4+3 ; h[k] via width-4 shuffle
    float A0[4], A1[4];
    int cb = q * 4;
#pragma unroll
    for (int i = 0; i < 4; i++) { A0[i] = sb[cb + i]; A1[i] = 0.0f; }
#pragma unroll
    for (int k = 0; k < HIDDEN; k++) {
        float comp = ((k & 3) == 0) ? h[0] : ((k & 3) == 1) ? h[1]
                   : ((k & 3) == 2) ? h[2] : h[3];
        float hk = __shfl_sync(0xffffffffu, comp, k >> 2, 4);
#pragma unroll
        for (int i = 0; i < 4; i++) {
            A0[i] = fmaf(hk, sw0[k][cb + i], A0[i]);
            A1[i] = fmaf(hk, sw1[k][cb + i], A1[i]);
        }
    }
    float4 o0;
    o0.x = A0[0]; o0.y = A0[1]; o0.z = A0[2]; o0.w = A0[3];
    ((float4*)g_hw)[node * 4 + q] = o0;
    uint2 hp;
    *(__half2*)&hp.x = __floats2half2_rn(dn * A1[0], dn * A1[1]);
    *(__half2*)&hp.y = __floats2half2_rn(dn * A1[2], dn * A1[3]);
    ((uint2*)g_hph)[node * 4 + q] = hp;
}

// ---- K5: layer-2 aggregation + log_softmax; resets cnt for next replay ----
__global__ void __launch_bounds__(128, 8)
k_agg2(float* __restrict__ out) {
    int gid  = blockIdx.x * blockDim.x + threadIdx.x;
    int node = gid >> 2;
    int q    = gid & 3;

    int len = g_cnt[node];
    if (q == 0) g_cnt[node] = 0;          // replay-idempotent
    float ac[4] = {0.f, 0.f, 0.f, 0.f};
    gather_all((const uint2*)g_hph, node, q, len, ac);

    float dn = g_dinv[node];
    float4 sf = ((const float4*)g_hw)[node * 4 + q];
    float L[4];
    L[0] = sf.x + dn * ac[0];
    L[1] = sf.y + dn * ac[1];
    L[2] = sf.z + dn * ac[2];
    L[3] = sf.w + dn * ac[3];

    // valid channels: lane0 c0..3, lane1 c4..7, lane2 c8..9, lane3 none
    int cb = q * 4;
    int nvalid = (cb < 8) ? 4 : (cb == 8 ? 2 : 0);
    float m = -1e30f;
#pragma unroll
    for (int i = 0; i < 4; i++) if (i < nvalid) m = fmaxf(m, L[i]);
#pragma unroll
    for (int o = 1; o < 4; o <<= 1)
        m = fmaxf(m, __shfl_xor_sync(0xffffffffu, m, o, 4));
    float s = 0.0f;
#pragma unroll
    for (int i = 0; i < 4; i++) if (i < nvalid) s += expf(L[i] - m);
#pragma unroll
    for (int o = 1; o < 4; o <<= 1)
        s += __shfl_xor_sync(0xffffffffu, s, o, 4);
    float lse = m + logf(s);

    float* op = out + (size_t)node * N_CLASSES;
    if (q < 2) {
        ((float2*)(op + cb))[0] = make_float2(L[0] - lse, L[1] - lse);
        ((float2*)(op + cb))[1] = make_float2(L[2] - lse, L[3] - lse);
    } else if (q == 2) {
        ((float2*)(op + 8))[0] = make_float2(L[0] - lse, L[1] - lse);
    }
}

// ---- host-side stream/event resources (created once at load; no device mem) ----
namespace {
struct ForkRes {
    cudaStream_t s2;
    cudaEvent_t evFork, evJoin;
    ForkRes() {
        cudaStreamCreateWithFlags(&s2, cudaStreamNonBlocking);
        cudaEventCreateWithFlags(&evFork, cudaEventDisableTiming);
        cudaEventCreateWithFlags(&evJoin, cudaEventDisableTiming);
    }
};
ForkRes g_fork;   // constructed before main
}

extern "C" void kernel_launch(void* const* d_in, const int* in_sizes, int n_in,
                              void* d_out, int out_size) {
    const float* x    = (const float*)d_in[0];
    const int*   ei   = (const int*)d_in[1];     // int32: JAX x64 disabled
    const float* w1_0 = (const float*)d_in[2];
    const float* w1_1 = (const float*)d_in[3];
    const float* b1   = (const float*)d_in[4];
    const float* w2_0 = (const float*)d_in[5];
    const float* w2_1 = (const float*)d_in[6];
    const float* b2   = (const float*)d_in[7];
    float* out = (float*)d_out;

    const int SB = (E4 + 255) / 256;               // 1563
    const int PB = (N_NODES + 255) / 256;          // 391
    const int GA = (N_NODES * 4) / 128;            // 3125, exact

    // fork: proj (independent of scatter) runs on s2, scatter on stream 0
    cudaEventRecord(g_fork.evFork, 0);
    cudaStreamWaitEvent(g_fork.s2, g_fork.evFork, 0);
    k_projU<<<PB, 256, 0, g_fork.s2>>>(x, w1_0, w1_1, b1);
    cudaEventRecord(g_fork.evJoin, g_fork.s2);

    k_scatter1<<<SB, 256>>>(ei);

    // join: everything after needs both branches
    cudaStreamWaitEvent(0, g_fork.evJoin, 0);
    k_scale <<<PB, 256>>>();
    k_agg1p2<<<GA, 128>>>(w2_0, w2_1, b2);
    k_agg2  <<<GA, 128>>>(out);
}

// round 15
// speedup vs baseline: 1.0335x; 1.0335x over previous
#include <cuda_runtime.h>
#include <cuda_fp16.h>
#include <math.h>

#define N_NODES   100000
#define N_EDGES   1600000
#define N_FEAT    50
#define HIDDEN    16
#define N_CLASSES 10
#define CAP       64           // bucket capacity; deg ~ Poisson(16), P(>=64)~2e-18
#define E2        (N_EDGES / 2)

typedef unsigned long long ull;

// ---- packed f32x2 helpers (sm_103a) ----
__device__ __forceinline__ ull pk2(float lo, float hi) {
    ull r;
    asm("mov.b64 %0, {%1, %2};" : "=l"(r) : "f"(lo), "f"(hi));
    return r;
}
__device__ __forceinline__ void upk2(float& lo, float& hi, ull v) {
    asm("mov.b64 {%0, %1}, %2;" : "=f"(lo), "=f"(hi) : "l"(v));
}
__device__ __forceinline__ ull fma2(ull a, ull b, ull c) {
    ull d;
    asm("fma.rn.f32x2 %0, %1, %2, %3;" : "=l"(d) : "l"(a), "l"(b), "l"(c));
    return d;
}

// ---- scratch (static device globals; zero-initialized at load) ----
// payload arrays have ONE extra row (index N_NODES) that is never written:
// it stays zero and absorbs gathers for out-of-range bucket slots.
__device__ int   g_cnt[N_NODES];              // bucket fill counts (reset by agg2)
__device__ float g_dinv[N_NODES];
__device__ __align__(16) int g_csrp[N_NODES * CAP];  // padded bucket CSR (src ids)
__device__ __align__(16) float  g_xw0[N_NODES * HIDDEN];         // x@w1_0 + b1
__device__ __align__(16) __half g_xp1h[(N_NODES + 1) * HIDDEN];  // fp16 dinv*(x@w1_1)
__device__ __align__(16) float  g_hw [N_NODES * HIDDEN];         // h@w2_0 + b2
__device__ __align__(16) __half g_hph[(N_NODES + 1) * HIDDEN];   // fp16 dinv*(h@w2_1)

// ---- K1: single-pass bucket scatter; 2 edges/thread, 128-thr blocks ----
__global__ void __launch_bounds__(128)
k_scatter1(const int* __restrict__ ei) {
    int e2 = blockIdx.x * blockDim.x + threadIdx.x;
    if (e2 >= E2) return;
    int2 s = ((const int2*)ei)[e2];
    int2 d = ((const int2*)(ei + N_EDGES))[e2];
    int p0 = atomicAdd(&g_cnt[d.x], 1);
    int p1 = atomicAdd(&g_cnt[d.y], 1);
    if (p0 < CAP) __stcs(&g_csrp[d.x * CAP + p0], s.x);
    if (p1 < CAP) __stcs(&g_csrp[d.y * CAP + p1], s.y);
}

// ---- K2: layer-1 projections, UNSCALED (no g_cnt dependency; runs || scatter) ----
__global__ void k_projU(const float* __restrict__ x,
                        const float* __restrict__ w0,
                        const float* __restrict__ w1,
                        const float* __restrict__ b1) {
    __shared__ ull sw0p[N_FEAT * HIDDEN / 2];
    __shared__ ull sw1p[N_FEAT * HIDDEN / 2];
    __shared__ float sb[HIDDEN];
    for (int i = threadIdx.x; i < N_FEAT * HIDDEN; i += blockDim.x) {
        ((float*)sw0p)[i] = w0[i];
        ((float*)sw1p)[i] = w1[i];
    }
    if (threadIdx.x < HIDDEN) sb[threadIdx.x] = b1[threadIdx.x];
    __syncthreads();

    int n = blockIdx.x * blockDim.x + threadIdx.x;
    if (n >= N_NODES) return;

    ull a0[8], a1[8];
    ull z = pk2(0.0f, 0.0f);
#pragma unroll
    for (int p = 0; p < 8; p++) { a0[p] = z; a1[p] = z; }

    const float2* xr = (const float2*)(x + (size_t)n * N_FEAT);  // 50 even
#pragma unroll 5
    for (int k2 = 0; k2 < N_FEAT / 2; k2++) {
        float2 xv = __ldg(&xr[k2]);
        ull xa = pk2(xv.x, xv.x);
        ull xb = pk2(xv.y, xv.y);
        const ull* w0a = sw0p + (2 * k2) * 8;
        const ull* w1a = sw1p + (2 * k2) * 8;
#pragma unroll
        for (int p = 0; p < 8; p++) {
            a0[p] = fma2(xa, w0a[p],     a0[p]);
            a0[p] = fma2(xb, w0a[8 + p], a0[p]);
            a1[p] = fma2(xa, w1a[p],     a1[p]);
            a1[p] = fma2(xb, w1a[8 + p], a1[p]);
        }
    }
    float4* o0 = (float4*)(g_xw0 + (size_t)n * HIDDEN);
    __half2 hx[8];
#pragma unroll
    for (int q = 0; q < 4; q++) {
        float v0a, v0b, v0c, v0d, v1a, v1b, v1c, v1d;
        upk2(v0a, v0b, a0[q * 2]);
        upk2(v0c, v0d, a0[q * 2 + 1]);
        upk2(v1a, v1b, a1[q * 2]);
        upk2(v1c, v1d, a1[q * 2 + 1]);
        float4 r0;
        r0.x = v0a + sb[q * 4 + 0];
        r0.y = v0b + sb[q * 4 + 1];
        r0.z = v0c + sb[q * 4 + 2];
        r0.w = v0d + sb[q * 4 + 3];
        o0[q] = r0;
        hx[q * 2 + 0] = __floats2half2_rn(v1a, v1b);
        hx[q * 2 + 1] = __floats2half2_rn(v1c, v1d);
    }
    uint4* oh = (uint4*)(g_xp1h + (size_t)n * HIDDEN);
    oh[0] = *(uint4*)&hx[0];
    oh[1] = *(uint4*)&hx[4];
}

// ---- K3: dinv from final cnt; scale xp1h in place (after join) ----
__global__ void k_scale() {
    int n = blockIdx.x * blockDim.x + threadIdx.x;
    if (n >= N_NODES) return;
    int d = g_cnt[n];
    float dn = (d > 0) ? rsqrtf((float)d) : 0.0f;
    g_dinv[n] = dn;
    uint4* p = (uint4*)(g_xp1h + (size_t)n * HIDDEN);
    uint4 v0 = p[0], v1 = p[1];
    __half2* h0 = (__half2*)&v0;
    __half2* h1 = (__half2*)&v1;
#pragma unroll
    for (int i = 0; i < 4; i++) {
        float2 f = __half22float2(h0[i]);
        h0[i] = __floats2half2_rn(dn * f.x, dn * f.y);
        f = __half22float2(h1[i]);
        h1[i] = __floats2half2_rn(dn * f.x, dn * f.y);
    }
    p[0] = v0;
    p[1] = v1;
}

// fp16 gather accumulate: v holds 4 half2 (8 channels)
__device__ __forceinline__ void acc_h8(float2* ac, uint4 v) {
    float2 f;
    f = __half22float2(*(__half2*)&v.x); ac[0].x += f.x; ac[0].y += f.y;
    f = __half22float2(*(__half2*)&v.y); ac[1].x += f.x; ac[1].y += f.y;
    f = __half22float2(*(__half2*)&v.z); ac[2].x += f.x; ac[2].y += f.y;
    f = __half22float2(*(__half2*)&v.w); ac[3].x += f.x; ac[3].y += f.y;
}

// branch-free 16-edge gather chunk (bucket storage is always CAP ints;
// out-of-range slots redirected to the zero row N_NODES).
__device__ __forceinline__ void gather16(const uint4* __restrict__ pay,
                                         const int* __restrict__ base,
                                         int j0, int len, int q, float2* ac) {
    const int4* ip = (const int4*)(base + j0);
    int4 ia = __ldg(&ip[0]);
    int4 ib = __ldg(&ip[1]);
    int4 ic = __ldg(&ip[2]);
    int4 id = __ldg(&ip[3]);
    int s[16];
    s[0]  = ia.x; s[1]  = ia.y; s[2]  = ia.z; s[3]  = ia.w;
    s[4]  = ib.x; s[5]  = ib.y; s[6]  = ib.z; s[7]  = ib.w;
    s[8]  = ic.x; s[9]  = ic.y; s[10] = ic.z; s[11] = ic.w;
    s[12] = id.x; s[13] = id.y; s[14] = id.z; s[15] = id.w;
    uint4 v[16];
#pragma unroll
    for (int k = 0; k < 16; k++) {
        int idx = (j0 + k < len) ? s[k] : N_NODES;   // zero row if past end
        v[k] = __ldg(&pay[idx * 2 + q]);
    }
#pragma unroll
    for (int k = 0; k < 16; k++) acc_h8(ac, v[k]);
}

__device__ __forceinline__ void gather_all(const uint4* __restrict__ pay,
                                           int node, int q, int len,
                                           float2* ac) {
    const int* base = g_csrp + node * CAP;
    gather16(pay, base, 0, len, q, ac);
    if (len > 16) {
        gather16(pay, base, 16, len, q, ac);
        if (len > 32) {
            gather16(pay, base, 32, len, q, ac);
            if (len > 48) gather16(pay, base, 48, len, q, ac);
        }
    }
}

// ---- K4: fused layer-1 agg + relu + layer-2 proj. 2 lanes/node ----
__global__ void __launch_bounds__(128, 6)
k_agg1p2(const float* __restrict__ w0,
         const float* __restrict__ w1,
         const float* __restrict__ b2) {
    __shared__ float sw0[HIDDEN][HIDDEN];   // [k][c], cols 10..15 = 0
    __shared__ float sw1[HIDDEN][HIDDEN];
    __shared__ float sb[HIDDEN];
    int t = threadIdx.x;
    for (int i = t; i < HIDDEN * HIDDEN; i += blockDim.x) {
        int k = i >> 4, c = i & 15;
        sw0[k][c] = (c < N_CLASSES) ? w0[k * N_CLASSES + c] : 0.0f;
        sw1[k][c] = (c < N_CLASSES) ? w1[k * N_CLASSES + c] : 0.0f;
    }
    if (t < HIDDEN) sb[t] = (t < N_CLASSES) ? b2[t] : 0.0f;
    __syncthreads();

    int gid  = blockIdx.x * blockDim.x + t;   // N_NODES*2 threads (guarded)
    int node = gid >> 1;
    int q    = gid & 1;
    if (node >= N_NODES) return;

    int len = g_cnt[node];
    float2 ac[4] = {{0.f,0.f},{0.f,0.f},{0.f,0.f},{0.f,0.f}};
    gather_all((const uint4*)g_xp1h, node, q, len, ac);

    float dn = g_dinv[node];
    const float4* xw = (const float4*)g_xw0;
    float4 f0 = xw[node * 4 + q * 2];
    float4 f1 = xw[node * 4 + q * 2 + 1];
    float h[8];
    h[0] = fmaxf(f0.x + dn * ac[0].x, 0.0f);
    h[1] = fmaxf(f0.y + dn * ac[0].y, 0.0f);
    h[2] = fmaxf(f0.z + dn * ac[1].x, 0.0f);
    h[3] = fmaxf(f0.w + dn * ac[1].y, 0.0f);
    h[4] = fmaxf(f1.x + dn * ac[2].x, 0.0f);
    h[5] = fmaxf(f1.y + dn * ac[2].y, 0.0f);
    h[6] = fmaxf(f1.z + dn * ac[3].x, 0.0f);
    h[7] = fmaxf(f1.w + dn * ac[3].y, 0.0f);

    // layer-2 projection: channels q*8..q*8+7 ; h[k] via width-2 shuffle
    float A0[8], A1[8];
    int cb = q * 8;
#pragma unroll
    for (int i = 0; i < 8; i++) { A0[i] = sb[cb + i]; A1[i] = 0.0f; }
#pragma unroll
    for (int k = 0; k < HIDDEN; k++) {
        float hk = __shfl_sync(0xffffffffu, h[k & 7], k >> 3, 2);
#pragma unroll
        for (int i = 0; i < 8; i++) {
            A0[i] = fmaf(hk, sw0[k][cb + i], A0[i]);
            A1[i] = fmaf(hk, sw1[k][cb + i], A1[i]);
        }
    }
    float4* hw = (float4*)g_hw;
    float4 o0, o1;
    o0.x = A0[0]; o0.y = A0[1]; o0.z = A0[2]; o0.w = A0[3];
    o1.x = A0[4]; o1.y = A0[5]; o1.z = A0[6]; o1.w = A0[7];
    hw[node * 4 + q * 2]     = o0;
    hw[node * 4 + q * 2 + 1] = o1;
    __half2 hp[4];
#pragma unroll
    for (int i = 0; i < 4; i++)
        hp[i] = __floats2half2_rn(dn * A1[2 * i], dn * A1[2 * i + 1]);
    ((uint4*)g_hph)[node * 2 + q] = *(uint4*)&hp[0];
}

// ---- K5: layer-2 aggregation + log_softmax; resets cnt for next replay ----
__global__ void __launch_bounds__(128, 6)
k_agg2(float* __restrict__ out) {
    int gid  = blockIdx.x * blockDim.x + threadIdx.x;
    int node = gid >> 1;
    int q    = gid & 1;
    if (node >= N_NODES) return;

    int len = g_cnt[node];
    if (q == 0) g_cnt[node] = 0;          // replay-idempotent
    float2 ac[4] = {{0.f,0.f},{0.f,0.f},{0.f,0.f},{0.f,0.f}};
    gather_all((const uint4*)g_hph, node, q, len, ac);

    float dn = g_dinv[node];
    const float4* hwv = (const float4*)g_hw;
    float4 f0 = hwv[node * 4 + q * 2];
    float4 f1 = hwv[node * 4 + q * 2 + 1];
    float L[8];
    L[0] = f0.x + dn * ac[0].x;
    L[1] = f0.y + dn * ac[0].y;
    L[2] = f0.z + dn * ac[1].x;
    L[3] = f0.w + dn * ac[1].y;
    L[4] = f1.x + dn * ac[2].x;
    L[5] = f1.y + dn * ac[2].y;
    L[6] = f1.z + dn * ac[3].x;
    L[7] = f1.w + dn * ac[3].y;

    // valid channels: lane 0 -> c0..7 (all), lane 1 -> c8,c9 (i<2)
    int nvalid = q ? 2 : 8;
    float m = -1e30f;
#pragma unroll
    for (int i = 0; i < 8; i++) if (i < nvalid) m = fmaxf(m, L[i]);
    m = fmaxf(m, __shfl_xor_sync(0xffffffffu, m, 1, 2));
    float s = 0.0f;
#pragma unroll
    for (int i = 0; i < 8; i++) if (i < nvalid) s += expf(L[i] - m);
    s += __shfl_xor_sync(0xffffffffu, s, 1, 2);
    float lse = m + logf(s);

    float* op = out + (size_t)node * N_CLASSES;
    if (q == 0) {
#pragma unroll
        for (int i = 0; i < 4; i++)
            ((float2*)op)[i] = make_float2(L[2 * i] - lse, L[2 * i + 1] - lse);
    } else {
        ((float2*)(op + 8))[0] = make_float2(L[0] - lse, L[1] - lse);
    }
}

// ---- host-side stream/event resources (created once at load; no device mem) ----
namespace {
struct ForkRes {
    cudaStream_t s2;
    cudaEvent_t evFork, evJoin;
    ForkRes() {
        cudaStreamCreateWithFlags(&s2, cudaStreamNonBlocking);
        cudaEventCreateWithFlags(&evFork, cudaEventDisableTiming);
        cudaEventCreateWithFlags(&evJoin, cudaEventDisableTiming);
    }
};
ForkRes g_fork;   // constructed before main
}

extern "C" void kernel_launch(void* const* d_in, const int* in_sizes, int n_in,
                              void* d_out, int out_size) {
    const float* x    = (const float*)d_in[0];
    const int*   ei   = (const int*)d_in[1];     // int32: JAX x64 disabled
    const float* w1_0 = (const float*)d_in[2];
    const float* w1_1 = (const float*)d_in[3];
    const float* b1   = (const float*)d_in[4];
    const float* w2_0 = (const float*)d_in[5];
    const float* w2_1 = (const float*)d_in[6];
    const float* b2   = (const float*)d_in[7];
    float* out = (float*)d_out;

    const int SB = (E2 + 127) / 128;               // 6250
    const int PB = (N_NODES + 255) / 256;          // 391
    const int GA = (N_NODES * 2 + 127) / 128;      // 1563

    // fork: proj (independent of scatter) runs on s2, scatter on stream 0
    cudaEventRecord(g_fork.evFork, 0);
    cudaStreamWaitEvent(g_fork.s2, g_fork.evFork, 0);
    k_projU<<<PB, 256, 0, g_fork.s2>>>(x, w1_0, w1_1, b1);
    cudaEventRecord(g_fork.evJoin, g_fork.s2);

    k_scatter1<<<SB, 128>>>(ei);

    // join: everything after needs both branches
    cudaStreamWaitEvent(0, g_fork.evJoin, 0);
    k_scale <<<PB, 256>>>();
    k_agg1p2<<<GA, 128>>>(w2_0, w2_1, b2);
    k_agg2  <<<GA, 128>>>(out);
}

// round 16
// speedup vs baseline: 1.0569x; 1.0227x over previous
#include <cuda_runtime.h>
#include <cuda_fp16.h>
#include <math.h>

#define N_NODES   100000
#define N_EDGES   1600000
#define N_FEAT    50
#define HIDDEN    16
#define N_CLASSES 10
#define CAP       64           // bucket capacity; deg ~ Poisson(16), P(>=64)~2e-18

typedef unsigned long long ull;

// ---- packed f32x2 helpers (sm_103a) ----
__device__ __forceinline__ ull pk2(float lo, float hi) {
    ull r;
    asm("mov.b64 %0, {%1, %2};" : "=l"(r) : "f"(lo), "f"(hi));
    return r;
}
__device__ __forceinline__ void upk2(float& lo, float& hi, ull v) {
    asm("mov.b64 {%0, %1}, %2;" : "=f"(lo), "=f"(hi) : "l"(v));
}
__device__ __forceinline__ ull fma2(ull a, ull b, ull c) {
    ull d;
    asm("fma.rn.f32x2 %0, %1, %2, %3;" : "=l"(d) : "l"(a), "l"(b), "l"(c));
    return d;
}

// ---- scratch (static device globals; zero-initialized at load) ----
// gathered payload arrays have ONE extra row (index N_NODES), never written:
// it stays zero and absorbs gathers for out-of-range bucket slots.
__device__ int   g_cnt[N_NODES];              // bucket fill counts (reset by agg2)
__device__ float g_dinv[N_NODES];
__device__ __align__(16) int g_csrp[N_NODES * CAP];  // padded bucket CSR (src ids)
__device__ __align__(16) __half g_xw0h[N_NODES * HIDDEN];        // fp16 x@w1_0 + b1
__device__ __align__(16) __half g_xp1h[(N_NODES + 1) * HIDDEN];  // fp16 dinv*(x@w1_1)
__device__ __align__(16) __half g_hwh [N_NODES * HIDDEN];        // fp16 h@w2_0 + b2
__device__ __align__(16) __half g_hph[(N_NODES + 1) * HIDDEN];   // fp16 dinv*(h@w2_1)

// ---- K1: single-pass bucket scatter; 1 edge/thread, fully coalesced ----
__global__ void __launch_bounds__(128)
k_scatter1(const int* __restrict__ ei) {
    int e = blockIdx.x * blockDim.x + threadIdx.x;
    if (e >= N_EDGES) return;
    int s = __ldg(&ei[e]);
    int d = __ldg(&ei[N_EDGES + e]);
    int p = atomicAdd(&g_cnt[d], 1);
    if (p < CAP) __stcs(&g_csrp[d * CAP + p], s);
}

// ---- K2: layer-1 projections, UNSCALED (no g_cnt dependency; runs || scatter) ----
// xw0h = fp16(x@w1_0 + b1) ; xp1h = fp16(x@w1_1)  [dinv applied by k_scale]
__global__ void k_projU(const float* __restrict__ x,
                        const float* __restrict__ w0,
                        const float* __restrict__ w1,
                        const float* __restrict__ b1) {
    __shared__ ull sw0p[N_FEAT * HIDDEN / 2];
    __shared__ ull sw1p[N_FEAT * HIDDEN / 2];
    __shared__ float sb[HIDDEN];
    for (int i = threadIdx.x; i < N_FEAT * HIDDEN; i += blockDim.x) {
        ((float*)sw0p)[i] = w0[i];
        ((float*)sw1p)[i] = w1[i];
    }
    if (threadIdx.x < HIDDEN) sb[threadIdx.x] = b1[threadIdx.x];
    __syncthreads();

    int n = blockIdx.x * blockDim.x + threadIdx.x;
    if (n >= N_NODES) return;

    ull a0[8], a1[8];
    ull z = pk2(0.0f, 0.0f);
#pragma unroll
    for (int p = 0; p < 8; p++) { a0[p] = z; a1[p] = z; }

    const float2* xr = (const float2*)(x + (size_t)n * N_FEAT);  // 50 even
#pragma unroll 5
    for (int k2 = 0; k2 < N_FEAT / 2; k2++) {
        float2 xv = __ldg(&xr[k2]);
        ull xa = pk2(xv.x, xv.x);
        ull xb = pk2(xv.y, xv.y);
        const ull* w0a = sw0p + (2 * k2) * 8;
        const ull* w1a = sw1p + (2 * k2) * 8;
#pragma unroll
        for (int p = 0; p < 8; p++) {
            a0[p] = fma2(xa, w0a[p],     a0[p]);
            a0[p] = fma2(xb, w0a[8 + p], a0[p]);
            a1[p] = fma2(xa, w1a[p],     a1[p]);
            a1[p] = fma2(xb, w1a[8 + p], a1[p]);
        }
    }
    __half2 hw2[8];
    __half2 hx[8];
#pragma unroll
    for (int q = 0; q < 4; q++) {
        float v0a, v0b, v0c, v0d, v1a, v1b, v1c, v1d;
        upk2(v0a, v0b, a0[q * 2]);
        upk2(v0c, v0d, a0[q * 2 + 1]);
        upk2(v1a, v1b, a1[q * 2]);
        upk2(v1c, v1d, a1[q * 2 + 1]);
        hw2[q * 2 + 0] = __floats2half2_rn(v0a + sb[q * 4 + 0], v0b + sb[q * 4 + 1]);
        hw2[q * 2 + 1] = __floats2half2_rn(v0c + sb[q * 4 + 2], v0d + sb[q * 4 + 3]);
        hx[q * 2 + 0]  = __floats2half2_rn(v1a, v1b);
        hx[q * 2 + 1]  = __floats2half2_rn(v1c, v1d);
    }
    uint4* ow = (uint4*)(g_xw0h + (size_t)n * HIDDEN);
    ow[0] = *(uint4*)&hw2[0];
    ow[1] = *(uint4*)&hw2[4];
    uint4* oh = (uint4*)(g_xp1h + (size_t)n * HIDDEN);
    oh[0] = *(uint4*)&hx[0];
    oh[1] = *(uint4*)&hx[4];
}

// ---- K3: dinv from final cnt; scale xp1h in place (after join) ----
__global__ void __launch_bounds__(128)
k_scale() {
    int n = blockIdx.x * blockDim.x + threadIdx.x;
    if (n >= N_NODES) return;
    int d = g_cnt[n];
    float dn = (d > 0) ? rsqrtf((float)d) : 0.0f;
    g_dinv[n] = dn;
    uint4* p = (uint4*)(g_xp1h + (size_t)n * HIDDEN);
    uint4 v0 = p[0], v1 = p[1];
    __half2* h0 = (__half2*)&v0;
    __half2* h1 = (__half2*)&v1;
#pragma unroll
    for (int i = 0; i < 4; i++) {
        float2 f = __half22float2(h0[i]);
        h0[i] = __floats2half2_rn(dn * f.x, dn * f.y);
        f = __half22float2(h1[i]);
        h1[i] = __floats2half2_rn(dn * f.x, dn * f.y);
    }
    p[0] = v0;
    p[1] = v1;
}

// fp16 gather accumulate: v holds 4 half2 (8 channels)
__device__ __forceinline__ void acc_h8(float2* ac, uint4 v) {
    float2 f;
    f = __half22float2(*(__half2*)&v.x); ac[0].x += f.x; ac[0].y += f.y;
    f = __half22float2(*(__half2*)&v.y); ac[1].x += f.x; ac[1].y += f.y;
    f = __half22float2(*(__half2*)&v.z); ac[2].x += f.x; ac[2].y += f.y;
    f = __half22float2(*(__half2*)&v.w); ac[3].x += f.x; ac[3].y += f.y;
}

// branch-free 16-edge gather chunk (bucket storage is always CAP ints;
// out-of-range slots redirected to the zero row N_NODES).
__device__ __forceinline__ void gather16(const uint4* __restrict__ pay,
                                         const int* __restrict__ base,
                                         int j0, int len, int q, float2* ac) {
    const int4* ip = (const int4*)(base + j0);
    int4 ia = __ldg(&ip[0]);
    int4 ib = __ldg(&ip[1]);
    int4 ic = __ldg(&ip[2]);
    int4 id = __ldg(&ip[3]);
    int s[16];
    s[0]  = ia.x; s[1]  = ia.y; s[2]  = ia.z; s[3]  = ia.w;
    s[4]  = ib.x; s[5]  = ib.y; s[6]  = ib.z; s[7]  = ib.w;
    s[8]  = ic.x; s[9]  = ic.y; s[10] = ic.z; s[11] = ic.w;
    s[12] = id.x; s[13] = id.y; s[14] = id.z; s[15] = id.w;
    uint4 v[16];
#pragma unroll
    for (int k = 0; k < 16; k++) {
        int idx = (j0 + k < len) ? s[k] : N_NODES;   // zero row if past end
        v[k] = __ldg(&pay[idx * 2 + q]);
    }
#pragma unroll
    for (int k = 0; k < 16; k++) acc_h8(ac, v[k]);
}

__device__ __forceinline__ void gather_all(const uint4* __restrict__ pay,
                                           int node, int q, int len,
                                           float2* ac) {
    const int* base = g_csrp + node * CAP;
    gather16(pay, base, 0, len, q, ac);
    if (len > 16) {
        gather16(pay, base, 16, len, q, ac);
        if (len > 32) {
            gather16(pay, base, 32, len, q, ac);
            if (len > 48) gather16(pay, base, 48, len, q, ac);
        }
    }
}

// ---- K4: fused layer-1 agg + relu + layer-2 proj. 2 lanes/node ----
__global__ void __launch_bounds__(128, 6)
k_agg1p2(const float* __restrict__ w0,
         const float* __restrict__ w1,
         const float* __restrict__ b2) {
    __shared__ float sw0[HIDDEN][HIDDEN];   // [k][c], cols 10..15 = 0
    __shared__ float sw1[HIDDEN][HIDDEN];
    __shared__ float sb[HIDDEN];
    int t = threadIdx.x;
    for (int i = t; i < HIDDEN * HIDDEN; i += blockDim.x) {
        int k = i >> 4, c = i & 15;
        sw0[k][c] = (c < N_CLASSES) ? w0[k * N_CLASSES + c] : 0.0f;
        sw1[k][c] = (c < N_CLASSES) ? w1[k * N_CLASSES + c] : 0.0f;
    }
    if (t < HIDDEN) sb[t] = (t < N_CLASSES) ? b2[t] : 0.0f;
    __syncthreads();

    int gid  = blockIdx.x * blockDim.x + t;   // N_NODES*2 threads (guarded)
    int node = gid >> 1;
    int q    = gid & 1;
    if (node >= N_NODES) return;

    int len = g_cnt[node];
    float2 ac[4] = {{0.f,0.f},{0.f,0.f},{0.f,0.f},{0.f,0.f}};
    gather_all((const uint4*)g_xp1h, node, q, len, ac);

    float dn = g_dinv[node];
    uint4 xf = ((const uint4*)g_xw0h)[node * 2 + q];
    __half2* xh = (__half2*)&xf;
    float2 e0 = __half22float2(xh[0]);
    float2 e1 = __half22float2(xh[1]);
    float2 e2 = __half22float2(xh[2]);
    float2 e3 = __half22float2(xh[3]);
    float h[8];
    h[0] = fmaxf(e0.x + dn * ac[0].x, 0.0f);
    h[1] = fmaxf(e0.y + dn * ac[0].y, 0.0f);
    h[2] = fmaxf(e1.x + dn * ac[1].x, 0.0f);
    h[3] = fmaxf(e1.y + dn * ac[1].y, 0.0f);
    h[4] = fmaxf(e2.x + dn * ac[2].x, 0.0f);
    h[5] = fmaxf(e2.y + dn * ac[2].y, 0.0f);
    h[6] = fmaxf(e3.x + dn * ac[3].x, 0.0f);
    h[7] = fmaxf(e3.y + dn * ac[3].y, 0.0f);

    // layer-2 projection: channels q*8..q*8+7 ; h[k] via width-2 shuffle
    float A0[8], A1[8];
    int cb = q * 8;
#pragma unroll
    for (int i = 0; i < 8; i++) { A0[i] = sb[cb + i]; A1[i] = 0.0f; }
#pragma unroll
    for (int k = 0; k < HIDDEN; k++) {
        float hk = __shfl_sync(0xffffffffu, h[k & 7], k >> 3, 2);
#pragma unroll
        for (int i = 0; i < 8; i++) {
            A0[i] = fmaf(hk, sw0[k][cb + i], A0[i]);
            A1[i] = fmaf(hk, sw1[k][cb + i], A1[i]);
        }
    }
    __half2 hwp[4];
#pragma unroll
    for (int i = 0; i < 4; i++)
        hwp[i] = __floats2half2_rn(A0[2 * i], A0[2 * i + 1]);
    ((uint4*)g_hwh)[node * 2 + q] = *(uint4*)&hwp[0];
    __half2 hp[4];
#pragma unroll
    for (int i = 0; i < 4; i++)
        hp[i] = __floats2half2_rn(dn * A1[2 * i], dn * A1[2 * i + 1]);
    ((uint4*)g_hph)[node * 2 + q] = *(uint4*)&hp[0];
}

// ---- K5: layer-2 aggregation + log_softmax; resets cnt for next replay ----
__global__ void __launch_bounds__(128, 6)
k_agg2(float* __restrict__ out) {
    int gid  = blockIdx.x * blockDim.x + threadIdx.x;
    int node = gid >> 1;
    int q    = gid & 1;
    if (node >= N_NODES) return;

    int len = g_cnt[node];
    if (q == 0) g_cnt[node] = 0;          // replay-idempotent
    float2 ac[4] = {{0.f,0.f},{0.f,0.f},{0.f,0.f},{0.f,0.f}};
    gather_all((const uint4*)g_hph, node, q, len, ac);

    float dn = g_dinv[node];
    uint4 hf = ((const uint4*)g_hwh)[node * 2 + q];
    __half2* hh = (__half2*)&hf;
    float2 e0 = __half22float2(hh[0]);
    float2 e1 = __half22float2(hh[1]);
    float2 e2 = __half22float2(hh[2]);
    float2 e3 = __half22float2(hh[3]);
    float L[8];
    L[0] = e0.x + dn * ac[0].x;
    L[1] = e0.y + dn * ac[0].y;
    L[2] = e1.x + dn * ac[1].x;
    L[3] = e1.y + dn * ac[1].y;
    L[4] = e2.x + dn * ac[2].x;
    L[5] = e2.y + dn * ac[2].y;
    L[6] = e3.x + dn * ac[3].x;
    L[7] = e3.y + dn * ac[3].y;

    // valid channels: lane 0 -> c0..7 (all), lane 1 -> c8,c9 (i<2)
    int nvalid = q ? 2 : 8;
    float m = -1e30f;
#pragma unroll
    for (int i = 0; i < 8; i++) if (i < nvalid) m = fmaxf(m, L[i]);
    m = fmaxf(m, __shfl_xor_sync(0xffffffffu, m, 1, 2));
    float s = 0.0f;
#pragma unroll
    for (int i = 0; i < 8; i++) if (i < nvalid) s += expf(L[i] - m);
    s += __shfl_xor_sync(0xffffffffu, s, 1, 2);
    float lse = m + logf(s);

    float* op = out + (size_t)node * N_CLASSES;
    if (q == 0) {
#pragma unroll
        for (int i = 0; i < 4; i++)
            ((float2*)op)[i] = make_float2(L[2 * i] - lse, L[2 * i + 1] - lse);
    } else {
        ((float2*)(op + 8))[0] = make_float2(L[0] - lse, L[1] - lse);
    }
}

// ---- host-side stream/event resources (created once at load; no device mem) ----
namespace {
struct ForkRes {
    cudaStream_t s2;
    cudaEvent_t evFork, evJoin;
    ForkRes() {
        cudaStreamCreateWithFlags(&s2, cudaStreamNonBlocking);
        cudaEventCreateWithFlags(&evFork, cudaEventDisableTiming);
        cudaEventCreateWithFlags(&evJoin, cudaEventDisableTiming);
    }
};
ForkRes g_fork;   // constructed before main
}

extern "C" void kernel_launch(void* const* d_in, const int* in_sizes, int n_in,
                              void* d_out, int out_size) {
    const float* x    = (const float*)d_in[0];
    const int*   ei   = (const int*)d_in[1];     // int32: JAX x64 disabled
    const float* w1_0 = (const float*)d_in[2];
    const float* w1_1 = (const float*)d_in[3];
    const float* b1   = (const float*)d_in[4];
    const float* w2_0 = (const float*)d_in[5];
    const float* w2_1 = (const float*)d_in[6];
    const float* b2   = (const float*)d_in[7];
    float* out = (float*)d_out;

    const int SB = (N_EDGES + 127) / 128;          // 12500
    const int PB = (N_NODES + 255) / 256;          // 391
    const int CB = (N_NODES + 127) / 128;          // 782
    const int GA = (N_NODES * 2 + 127) / 128;      // 1563

    // fork: proj (independent of scatter) runs on s2, scatter on stream 0
    cudaEventRecord(g_fork.evFork, 0);
    cudaStreamWaitEvent(g_fork.s2, g_fork.evFork, 0);
    k_projU<<<PB, 256, 0, g_fork.s2>>>(x, w1_0, w1_1, b1);
    cudaEventRecord(g_fork.evJoin, g_fork.s2);

    k_scatter1<<<SB, 128>>>(ei);

    // join: everything after needs both branches
    cudaStreamWaitEvent(0, g_fork.evJoin, 0);
    k_scale <<<CB, 128>>>();
    k_agg1p2<<<GA, 128>>>(w2_0, w2_1, b2);
    k_agg2  <<<GA, 128>>>(out);
}